// round 8
// baseline (speedup 1.0000x reference)
#include <cuda_runtime.h>
#include <cuda_bf16.h>
#include <cstdint>

#define BB 4
#define LL 1024
#define DD 512
#define HH 8
#define HD 64

// ---------------------------------------------------------------------------
// Device scratch (static: no allocations allowed)
__device__ __align__(256) float g_S[(size_t)BB * HH * LL * LL];           // 128 MB scores
__device__ __align__(256) __nv_bfloat16 g_Phi[(size_t)BB * HH * LL * LL]; // 64 MB
__device__ __align__(256) __nv_bfloat16 g_Plo[(size_t)BB * HH * LL * LL]; // 64 MB
__device__ __align__(256) __nv_bfloat16 g_Khi[(size_t)BB * HH * LL * HD];
__device__ __align__(256) __nv_bfloat16 g_Klo[(size_t)BB * HH * LL * HD];
__device__ __align__(256) __nv_bfloat16 g_Qhi[(size_t)BB * HH * LL * HD];
__device__ __align__(256) __nv_bfloat16 g_Qlo[(size_t)BB * HH * LL * HD];
__device__ __align__(256) __nv_bfloat16 g_Vthi[(size_t)BB * HH * HD * LL]; // [bh][d][m]
__device__ __align__(256) __nv_bfloat16 g_Vtlo[(size_t)BB * HH * HD * LL];
__device__ float g_wacc[BB * LL];

// ---------------------------------------------------------------------------
__device__ __forceinline__ uint32_t smem_u32(const void* p) {
    uint32_t a;
    asm("{ .reg .u64 t; cvta.to.shared.u64 t, %1; cvt.u32.u64 %0, t; }" : "=r"(a) : "l"(p));
    return a;
}
__device__ __forceinline__ void ldm_x4(uint32_t& r0, uint32_t& r1, uint32_t& r2,
                                       uint32_t& r3, uint32_t addr) {
    asm volatile("ldmatrix.sync.aligned.m8n8.x4.shared.b16 {%0,%1,%2,%3}, [%4];"
                 : "=r"(r0), "=r"(r1), "=r"(r2), "=r"(r3) : "r"(addr));
}
__device__ __forceinline__ void mma_bf16(float& c0, float& c1, float& c2, float& c3,
                                         uint32_t a0, uint32_t a1, uint32_t a2, uint32_t a3,
                                         uint32_t b0, uint32_t b1) {
    asm volatile("mma.sync.aligned.m16n8k16.row.col.f32.bf16.bf16.f32 "
                 "{%0,%1,%2,%3}, {%4,%5,%6,%7}, {%8,%9}, {%0,%1,%2,%3};"
                 : "+f"(c0), "+f"(c1), "+f"(c2), "+f"(c3)
                 : "r"(a0), "r"(a1), "r"(a2), "r"(a3), "r"(b0), "r"(b1));
}

// smem row stride for MMA tiles: 40 bf16 = 80 B; conflict-free ldmatrix.
#define SSTR 40

__device__ __forceinline__ uint16_t bf16_bits(float f) {
    return __bfloat16_as_ushort(__float2bfloat16(f));
}

// ---------------------------------------------------------------------------
// Prep 1: split K,Q fp32 -> bf16 hi/lo in [bh][l][64] layout; zero wacc.
__global__ __launch_bounds__(256) void prep_kq_kernel(
    const float* __restrict__ Kp, const float* __restrict__ Qp)
{
    int idx = blockIdx.x * 256 + threadIdx.x;
    int k = idx & 63, h = (idx >> 6) & 7, l = (idx >> 9) & 1023, b = idx >> 19;
    size_t o = (((size_t)(b * 8 + h) * 1024 + l) << 6) | (unsigned)k;
    float kv = Kp[idx];
    __nv_bfloat16 khi = __float2bfloat16(kv);
    g_Khi[o] = khi;
    g_Klo[o] = __float2bfloat16(kv - __bfloat162float(khi));
    float qv = Qp[idx];
    __nv_bfloat16 qhi = __float2bfloat16(qv);
    g_Qhi[o] = qhi;
    g_Qlo[o] = __float2bfloat16(qv - __bfloat162float(qhi));
    if (idx < BB * LL) g_wacc[idx] = 0.f;
}

// Prep 2: transpose-split V [b][m][h*64+d] -> Vt hi/lo [bh][d][m]
__global__ __launch_bounds__(256) void prep_v_kernel(const float* __restrict__ Vp)
{
    __shared__ float t[32][33];
    int b = blockIdx.z;
    int m0 = blockIdx.x * 32, hd0 = blockIdx.y * 32;
    int tx = threadIdx.x, ty = threadIdx.y;   // (32, 8)
#pragma unroll
    for (int i = 0; i < 4; i++)
        t[ty + 8 * i][tx] = Vp[((size_t)b * 1024 + m0 + ty + 8 * i) * 512 + hd0 + tx];
    __syncthreads();
#pragma unroll
    for (int i = 0; i < 4; i++) {
        int hd = hd0 + ty + 8 * i;
        int h = hd >> 6, d = hd & 63;
        float x = t[tx][ty + 8 * i];
        __nv_bfloat16 hi = __float2bfloat16(x);
        size_t o = ((size_t)(b * 8 + h) * 64 + d) * 1024 + m0 + tx;
        g_Vthi[o] = hi;
        g_Vtlo[o] = __float2bfloat16(x - __bfloat162float(hi));
    }
}

// ---------------------------------------------------------------------------
// GEMM1 (mma.sync bf16): S[bh][l][m] = K[l,:]·Q[m,:], tile 128x128, K=64.
__global__ __launch_bounds__(256) void gemm1_kernel(const float* __restrict__ doc)
{
    __shared__ __nv_bfloat16 sA[2][128 * SSTR];
    __shared__ __nv_bfloat16 sB[2][128 * SSTR];

    int bh = blockIdx.z;
    int b = bh >> 3;
    int len = (int)doc[b];
    int l0 = blockIdx.y * 128, m0 = blockIdx.x * 128;
    if (l0 >= len || m0 >= len) return;

    int tid = threadIdx.x, wid = tid >> 5, lane = tid & 31;
    int wm = (wid >> 2) * 64, wn = (wid & 3) * 32;

    const uint4* srcA[2] = { (const uint4*)(g_Khi + ((size_t)bh * 1024 + l0) * 64),
                             (const uint4*)(g_Klo + ((size_t)bh * 1024 + l0) * 64) };
    const uint4* srcB[2] = { (const uint4*)(g_Qhi + ((size_t)bh * 1024 + m0) * 64),
                             (const uint4*)(g_Qlo + ((size_t)bh * 1024 + m0) * 64) };

    float c[4][4][4];
#pragma unroll
    for (int i = 0; i < 4; i++)
#pragma unroll
        for (int j = 0; j < 4; j++)
#pragma unroll
            for (int q = 0; q < 4; q++) c[i][j][q] = 0.f;

    uint32_t aoff = (uint32_t)(wm + (lane & 15)) * (SSTR * 2) + (((uint32_t)lane >> 4) << 4);
    uint32_t boff = (uint32_t)(wn + (lane & 7) + (((uint32_t)lane >> 4) << 3)) * (SSTR * 2)
                  + ((((uint32_t)lane >> 3) & 1) << 4);
    uint32_t sAh = smem_u32(&sA[0][0]), sAl = smem_u32(&sA[1][0]);
    uint32_t sBh = smem_u32(&sB[0][0]), sBl = smem_u32(&sB[1][0]);

    for (int kc = 0; kc < 64; kc += 32) {
        if (kc) __syncthreads();
#pragma unroll
        for (int e = 0; e < 2; e++) {
#pragma unroll
            for (int i = 0; i < 2; i++) {
                int idx = tid + i * 256;
                int row = idx >> 2, c4 = idx & 3;
                *(uint4*)((char*)&sA[e][0] + row * (SSTR * 2) + c4 * 16) =
                    srcA[e][(size_t)row * 8 + (kc >> 3) + c4];
                *(uint4*)((char*)&sB[e][0] + row * (SSTR * 2) + c4 * 16) =
                    srcB[e][(size_t)row * 8 + (kc >> 3) + c4];
            }
        }
        __syncthreads();

#pragma unroll
        for (int ks = 0; ks < 2; ks++) {
            uint32_t k0b = ks * 32;
            uint32_t Ah[4][4], Al[4][4], Bh[2][4], Bl[2][4];
#pragma unroll
            for (int mt = 0; mt < 4; mt++) {
                ldm_x4(Ah[mt][0], Ah[mt][1], Ah[mt][2], Ah[mt][3],
                       sAh + aoff + mt * 16 * (SSTR * 2) + k0b);
                ldm_x4(Al[mt][0], Al[mt][1], Al[mt][2], Al[mt][3],
                       sAl + aoff + mt * 16 * (SSTR * 2) + k0b);
            }
#pragma unroll
            for (int nt = 0; nt < 2; nt++) {
                ldm_x4(Bh[nt][0], Bh[nt][1], Bh[nt][2], Bh[nt][3],
                       sBh + boff + nt * 16 * (SSTR * 2) + k0b);
                ldm_x4(Bl[nt][0], Bl[nt][1], Bl[nt][2], Bl[nt][3],
                       sBl + boff + nt * 16 * (SSTR * 2) + k0b);
            }
#pragma unroll
            for (int mt = 0; mt < 4; mt++)
#pragma unroll
                for (int ns = 0; ns < 4; ns++) {
                    float* cc = c[mt][ns];
                    uint32_t* bh_ = &Bh[ns >> 1][(ns & 1) * 2];
                    uint32_t* bl_ = &Bl[ns >> 1][(ns & 1) * 2];
                    mma_bf16(cc[0], cc[1], cc[2], cc[3],
                             Ah[mt][0], Ah[mt][1], Ah[mt][2], Ah[mt][3], bh_[0], bh_[1]);
                    mma_bf16(cc[0], cc[1], cc[2], cc[3],
                             Ah[mt][0], Ah[mt][1], Ah[mt][2], Ah[mt][3], bl_[0], bl_[1]);
                    mma_bf16(cc[0], cc[1], cc[2], cc[3],
                             Al[mt][0], Al[mt][1], Al[mt][2], Al[mt][3], bh_[0], bh_[1]);
                }
        }
    }

    float* Sp = g_S + ((size_t)bh * 1024 + l0) * 1024 + m0;
#pragma unroll
    for (int mt = 0; mt < 4; mt++) {
        int r0 = wm + mt * 16 + (lane >> 2);
#pragma unroll
        for (int ns = 0; ns < 4; ns++) {
            int n = wn + ns * 8 + (lane & 3) * 2;
            *(float2*)&Sp[(size_t)r0 * 1024 + n] = make_float2(c[mt][ns][0], c[mt][ns][1]);
            *(float2*)&Sp[(size_t)(r0 + 8) * 1024 + n] = make_float2(c[mt][ns][2], c[mt][ns][3]);
        }
    }
}

// ---------------------------------------------------------------------------
// lnsm v3: smem-resident (high occupancy) but only 3 sweeps:
//  1) LN pass (strided m, coalesced LDG.32) + fold per-head max; sentinel -1e30
//     for m in [len, 1024) so later passes are mask-free.
//  2) exp+sum pass (vectorized m0=4*tid, LDS.128/STS.128).
//  3) store pass: scale by 1/sum here, pack bf16 hi/lo, STG.64 + col-sum atomics.
__global__ __launch_bounds__(256) void lnsm_kernel(
    const float* __restrict__ doc, const float* __restrict__ gamma,
    const float* __restrict__ beta)
{
    __shared__ float s[HH][LL];       // 32 KB
    __shared__ float sred[HH][8];
    __shared__ float bout[HH];

    int b = blockIdx.y, l = blockIdx.x;
    int len = (int)doc[b];
    int kend  = (len + 63) & ~63;
    int lceil = (len + 127) & ~127;
    int tid = threadIdx.x;
    int wid = tid >> 5, lane = tid & 31;

    if (l >= len) {                    // zero rows needed by GEMM2
        if (l >= lceil) return;
        int m0 = tid * 4;
        if (m0 < kend) {
            uint2 z = make_uint2(0u, 0u);
#pragma unroll
            for (int h = 0; h < HH; ++h) {
                size_t o = ((size_t)(b * 8 + h) * 1024 + l) * 1024 + m0;
                *(uint2*)(g_Phi + o) = z;
                *(uint2*)(g_Plo + o) = z;
            }
        }
        return;
    }

    const float* Sb = g_S + ((size_t)(b * 8) * 1024 + l) * 1024;
    float ga[HH], be[HH];
#pragma unroll
    for (int h = 0; h < HH; h++) { ga[h] = gamma[h]; be[h] = beta[h]; }

    // ---- pass 1: LN + per-thread max; sentinel beyond len ----
    float mx[HH];
#pragma unroll
    for (int h = 0; h < HH; h++) mx[h] = -1e30f;

    for (int m = tid; m < LL; m += 256) {
        if (m < len) {
            float x[HH];
#pragma unroll
            for (int h = 0; h < HH; h++) x[h] = Sb[((size_t)h << 20) + m];
            float mu = 0.f;
#pragma unroll
            for (int h = 0; h < HH; h++) mu += x[h];
            mu *= (1.f / HH);
            float var = 0.f;
#pragma unroll
            for (int h = 0; h < HH; h++) { float d0 = x[h] - mu; var += d0 * d0; }
            var *= (1.f / HH);
            float rstd = rsqrtf(var + 1e-5f);
#pragma unroll
            for (int h = 0; h < HH; h++) {
                float v = (x[h] - mu) * rstd * ga[h] + be[h];
                s[h][m] = v;
                mx[h] = fmaxf(mx[h], v);
            }
        } else {
#pragma unroll
            for (int h = 0; h < HH; h++) s[h][m] = -1e30f;   // exp -> 0
        }
    }

    // block-reduce max per head
#pragma unroll
    for (int h = 0; h < HH; h++) {
#pragma unroll
        for (int o = 16; o; o >>= 1)
            mx[h] = fmaxf(mx[h], __shfl_xor_sync(0xffffffffu, mx[h], o));
    }
    if (lane == 0) {
#pragma unroll
        for (int h = 0; h < HH; h++) sred[h][wid] = mx[h];
    }
    __syncthreads();                   // also makes s[][] visible block-wide
    if (tid < 64) {
        int head = tid >> 3, slot = tid & 7;
        float v = sred[head][slot];
        v = fmaxf(v, __shfl_xor_sync(0xffffffffu, v, 4));
        v = fmaxf(v, __shfl_xor_sync(0xffffffffu, v, 2));
        v = fmaxf(v, __shfl_xor_sync(0xffffffffu, v, 1));
        if (slot == 0) bout[head] = v;
    }
    __syncthreads();
    float bmx[HH];
#pragma unroll
    for (int h = 0; h < HH; h++) bmx[h] = bout[h];

    // ---- pass 2: exp in place + per-head sums (vectorized, mask-free) ----
    int m0 = tid * 4;
    float sm[HH];
#pragma unroll
    for (int h = 0; h < HH; h++) sm[h] = 0.f;
#pragma unroll
    for (int h = 0; h < HH; h++) {
        float4 v = *(float4*)&s[h][m0];
        v.x = __expf(v.x - bmx[h]);
        v.y = __expf(v.y - bmx[h]);
        v.z = __expf(v.z - bmx[h]);
        v.w = __expf(v.w - bmx[h]);
        sm[h] += (v.x + v.y) + (v.z + v.w);
        *(float4*)&s[h][m0] = v;
    }

#pragma unroll
    for (int h = 0; h < HH; h++) {
#pragma unroll
        for (int o = 16; o; o >>= 1)
            sm[h] += __shfl_xor_sync(0xffffffffu, sm[h], o);
    }
    __syncthreads();                   // pass-2 writes done before sred reuse read
    if (lane == 0) {
#pragma unroll
        for (int h = 0; h < HH; h++) sred[h][wid] = sm[h];
    }
    __syncthreads();
    if (tid < 64) {
        int head = tid >> 3, slot = tid & 7;
        float v = sred[head][slot];
        v += __shfl_xor_sync(0xffffffffu, v, 4);
        v += __shfl_xor_sync(0xffffffffu, v, 2);
        v += __shfl_xor_sync(0xffffffffu, v, 1);
        if (slot == 0) bout[head] = v;
    }
    __syncthreads();
    float inv[HH];
#pragma unroll
    for (int h = 0; h < HH; h++) inv[h] = 1.f / bout[h];

    // ---- pass 3: scale + bf16 hi/lo emit + column sums ----
    if (m0 < kend) {
        float csum[4] = {0.f, 0.f, 0.f, 0.f};
#pragma unroll
        for (int h = 0; h < HH; ++h) {
            float4 v = *(float4*)&s[h][m0];
            float p0 = v.x * inv[h], p1 = v.y * inv[h];
            float p2 = v.z * inv[h], p3 = v.w * inv[h];
            csum[0] += p0; csum[1] += p1; csum[2] += p2; csum[3] += p3;
            uint16_t h0 = bf16_bits(p0), h1 = bf16_bits(p1);
            uint16_t h2 = bf16_bits(p2), h3 = bf16_bits(p3);
            uint32_t hp0 = (uint32_t)h0 | ((uint32_t)h1 << 16);
            uint32_t hp1 = (uint32_t)h2 | ((uint32_t)h3 << 16);
            uint16_t l0b = bf16_bits(p0 - __bfloat162float(__ushort_as_bfloat16(h0)));
            uint16_t l1b = bf16_bits(p1 - __bfloat162float(__ushort_as_bfloat16(h1)));
            uint16_t l2b = bf16_bits(p2 - __bfloat162float(__ushort_as_bfloat16(h2)));
            uint16_t l3b = bf16_bits(p3 - __bfloat162float(__ushort_as_bfloat16(h3)));
            uint32_t lp0 = (uint32_t)l0b | ((uint32_t)l1b << 16);
            uint32_t lp1 = (uint32_t)l2b | ((uint32_t)l3b << 16);
            size_t o = ((size_t)(b * 8 + h) * 1024 + l) * 1024 + m0;
            *(uint2*)(g_Phi + o) = make_uint2(hp0, hp1);
            *(uint2*)(g_Plo + o) = make_uint2(lp0, lp1);
        }
#pragma unroll
        for (int mi = 0; mi < 4; mi++)
            if (m0 + mi < len) atomicAdd(&g_wacc[b * 1024 + m0 + mi], csum[mi]);
    }
}

// ---------------------------------------------------------------------------
// Finalize w: one 1024-thread block per batch, single pass.
__global__ __launch_bounds__(1024) void wfin_kernel(
    const float* __restrict__ doc, float* __restrict__ wout)
{
    __shared__ float red[32];
    __shared__ float s_bmax, s_inv;
    int b = blockIdx.x;
    int len = (int)doc[b];
    int tid = threadIdx.x, w = tid >> 5, lane = tid & 31;
    float scale = 1.f / (8.f * (float)len);

    float v = (tid < len) ? g_wacc[b * LL + tid] * scale : -1e30f;
    float mx = v;
#pragma unroll
    for (int o = 16; o; o >>= 1) mx = fmaxf(mx, __shfl_xor_sync(0xffffffffu, mx, o));
    if (lane == 0) red[w] = mx;
    __syncthreads();
    if (w == 0) {
        float t = red[lane];
#pragma unroll
        for (int o = 16; o; o >>= 1) t = fmaxf(t, __shfl_xor_sync(0xffffffffu, t, o));
        if (lane == 0) s_bmax = t;
    }
    __syncthreads();
    float e = (tid < len) ? __expf(v - s_bmax) : 0.f;
    float sum = e;
#pragma unroll
    for (int o = 16; o; o >>= 1) sum += __shfl_xor_sync(0xffffffffu, sum, o);
    if (lane == 0) red[w] = sum;
    __syncthreads();
    if (w == 0) {
        float t = red[lane];
#pragma unroll
        for (int o = 16; o; o >>= 1) t += __shfl_xor_sync(0xffffffffu, t, o);
        if (lane == 0) s_inv = 1.f / t;
    }
    __syncthreads();
    wout[b * LL + tid] = e * s_inv;
}

// ---------------------------------------------------------------------------
// GEMM2 (mma.sync bf16): out[l,d] = sum_m P[l,m]·Vt[d,m]; tile 128(l) x 64(d).
// Register-prefetch pipeline over K chunks of 32 (next chunk's LDGs overlap MMA).
__global__ __launch_bounds__(256) void gemm2_kernel(
    const float* __restrict__ doc, float* __restrict__ outp)
{
    __shared__ __nv_bfloat16 sP[2][128 * SSTR];
    __shared__ __nv_bfloat16 sV[2][64 * SSTR];

    int b = blockIdx.z, h = blockIdx.y;
    int bh = b * 8 + h;
    int len = (int)doc[b];
    int l0 = blockIdx.x * 128;
    int tid = threadIdx.x, wid = tid >> 5, lane = tid & 31;

    if (l0 >= len) {
        float* dst = outp + ((size_t)b * 1024 + l0 + (tid >> 1)) * 512 + h * 64;
        float4 z = make_float4(0, 0, 0, 0);
#pragma unroll
        for (int j = 0; j < 8; j++) ((float4*)dst)[(tid & 1) * 8 + j] = z;
        return;
    }

    int wm = (wid >> 1) * 32, wn = (wid & 1) * 32;

    const uint4* srcP[2] = { (const uint4*)(g_Phi + ((size_t)bh * 1024 + l0) * 1024),
                             (const uint4*)(g_Plo + ((size_t)bh * 1024 + l0) * 1024) };
    const uint4* srcV[2] = { (const uint4*)(g_Vthi + (size_t)bh * 64 * 1024),
                             (const uint4*)(g_Vtlo + (size_t)bh * 64 * 1024) };

    float c[2][4][4];
#pragma unroll
    for (int i = 0; i < 2; i++)
#pragma unroll
        for (int j = 0; j < 4; j++)
#pragma unroll
            for (int q = 0; q < 4; q++) c[i][j][q] = 0.f;

    uint32_t aoff = (uint32_t)(wm + (lane & 15)) * (SSTR * 2) + (((uint32_t)lane >> 4) << 4);
    uint32_t boff = (uint32_t)(wn + (lane & 7) + (((uint32_t)lane >> 4) << 3)) * (SSTR * 2)
                  + ((((uint32_t)lane >> 3) & 1) << 4);
    uint32_t sPh = smem_u32(&sP[0][0]), sPl = smem_u32(&sP[1][0]);
    uint32_t sVh = smem_u32(&sV[0][0]), sVl = smem_u32(&sV[1][0]);

    int prow = tid >> 2, pc4 = tid & 3;
    int vrow = tid >> 2, vc4 = tid & 3;
    char* stP[2][2];
    char* stV[2];
#pragma unroll
    for (int e = 0; e < 2; e++) {
        stP[e][0] = (char*)&sP[e][0] + prow * (SSTR * 2) + pc4 * 16;
        stP[e][1] = (char*)&sP[e][0] + (prow + 64) * (SSTR * 2) + pc4 * 16;
        stV[e]    = (char*)&sV[e][0] + vrow * (SSTR * 2) + vc4 * 16;
    }

    int kend = (len + 31) & ~31;
    int nch = kend >> 5;

    uint4 rp[2][2], rv[2];
#pragma unroll
    for (int e = 0; e < 2; e++) {
        rp[e][0] = srcP[e][(size_t)prow * 128 + pc4];
        rp[e][1] = srcP[e][(size_t)(prow + 64) * 128 + pc4];
        rv[e]    = srcV[e][(size_t)vrow * 128 + vc4];
    }

    for (int ch = 0; ch < nch; ++ch) {
#pragma unroll
        for (int e = 0; e < 2; e++) {
            *(uint4*)stP[e][0] = rp[e][0];
            *(uint4*)stP[e][1] = rp[e][1];
            *(uint4*)stV[e]    = rv[e];
        }
        __syncthreads();

        if (ch + 1 < nch) {
            int mq = (ch + 1) * 4;
#pragma unroll
            for (int e = 0; e < 2; e++) {
                rp[e][0] = srcP[e][(size_t)prow * 128 + mq + pc4];
                rp[e][1] = srcP[e][(size_t)(prow + 64) * 128 + mq + pc4];
                rv[e]    = srcV[e][(size_t)vrow * 128 + mq + vc4];
            }
        }

#pragma unroll
        for (int ks = 0; ks < 2; ks++) {
            uint32_t k0b = ks * 32;
            uint32_t Ah[2][4], Al[2][4], Bh[2][4], Bl[2][4];
#pragma unroll
            for (int mt = 0; mt < 2; mt++) {
                ldm_x4(Ah[mt][0], Ah[mt][1], Ah[mt][2], Ah[mt][3],
                       sPh + aoff + mt * 16 * (SSTR * 2) + k0b);
                ldm_x4(Al[mt][0], Al[mt][1], Al[mt][2], Al[mt][3],
                       sPl + aoff + mt * 16 * (SSTR * 2) + k0b);
            }
#pragma unroll
            for (int nt = 0; nt < 2; nt++) {
                ldm_x4(Bh[nt][0], Bh[nt][1], Bh[nt][2], Bh[nt][3],
                       sVh + boff + nt * 16 * (SSTR * 2) + k0b);
                ldm_x4(Bl[nt][0], Bl[nt][1], Bl[nt][2], Bl[nt][3],
                       sVl + boff + nt * 16 * (SSTR * 2) + k0b);
            }
#pragma unroll
            for (int mt = 0; mt < 2; mt++)
#pragma unroll
                for (int ns = 0; ns < 4; ns++) {
                    float* cc = c[mt][ns];
                    uint32_t* bh_ = &Bh[ns >> 1][(ns & 1) * 2];
                    uint32_t* bl_ = &Bl[ns >> 1][(ns & 1) * 2];
                    mma_bf16(cc[0], cc[1], cc[2], cc[3],
                             Ah[mt][0], Ah[mt][1], Ah[mt][2], Ah[mt][3], bh_[0], bh_[1]);
                    mma_bf16(cc[0], cc[1], cc[2], cc[3],
                             Ah[mt][0], Ah[mt][1], Ah[mt][2], Ah[mt][3], bl_[0], bl_[1]);
                    mma_bf16(cc[0], cc[1], cc[2], cc[3],
                             Al[mt][0], Al[mt][1], Al[mt][2], Al[mt][3], bh_[0], bh_[1]);
                }
        }
        __syncthreads();
    }

    float* dstb = outp + ((size_t)b * 1024 + l0) * 512 + h * 64;
#pragma unroll
    for (int mt = 0; mt < 2; mt++) {
        int r0 = wm + mt * 16 + (lane >> 2);
#pragma unroll
        for (int ns = 0; ns < 4; ns++) {
            int n = wn + ns * 8 + (lane & 3) * 2;
            *(float2*)&dstb[(size_t)r0 * 512 + n] = make_float2(c[mt][ns][0], c[mt][ns][1]);
            *(float2*)&dstb[(size_t)(r0 + 8) * 512 + n] = make_float2(c[mt][ns][2], c[mt][ns][3]);
        }
    }
}

// ---------------------------------------------------------------------------
extern "C" void kernel_launch(void* const* d_in, const int* in_sizes, int n_in,
                              void* d_out, int out_size) {
    const float* K     = (const float*)d_in[0];
    const float* Q     = (const float*)d_in[1];
    const float* V     = (const float*)d_in[2];
    const float* doc   = (const float*)d_in[3];
    const float* gamma = (const float*)d_in[4];
    const float* beta  = (const float*)d_in[5];
    // pad_mask / bx_packed derivable from doc_sizes; unused.

    float* outp = (float*)d_out;

    prep_kq_kernel<<<(BB * LL * DD) / 256, 256>>>(K, Q);
    prep_v_kernel<<<dim3(LL / 32, DD / 32, BB), dim3(32, 8)>>>(V);

    dim3 g1(LL / 128, LL / 128, BB * HH);      // (8, 8, 32)
    gemm1_kernel<<<g1, 256>>>(doc);

    dim3 g2(LL, BB);
    lnsm_kernel<<<g2, 256>>>(doc, gamma, beta);

    if (out_size >= BB * LL * DD + BB * LL) {
        float* wout = outp + (size_t)BB * LL * DD;
        wfin_kernel<<<BB, 1024>>>(doc, wout);
    }

    dim3 g3(LL / 128, HH, BB);                 // (8, 8, 4)
    gemm2_kernel<<<g3, 256>>>(doc, outp);
}

// round 9
// speedup vs baseline: 1.0398x; 1.0398x over previous
#include <cuda_runtime.h>
#include <cuda_bf16.h>
#include <cstdint>

#define BB 4
#define LL 1024
#define DD 512
#define HH 8
#define HD 64

// ---------------------------------------------------------------------------
// Device scratch (static: no allocations allowed)
__device__ __align__(256) float g_S[(size_t)BB * HH * LL * LL];           // 128 MB scores
__device__ __align__(256) __nv_bfloat16 g_Phi[(size_t)BB * HH * LL * LL]; // 64 MB
__device__ __align__(256) __nv_bfloat16 g_Plo[(size_t)BB * HH * LL * LL]; // 64 MB
__device__ __align__(256) __nv_bfloat16 g_Khi[(size_t)BB * HH * LL * HD];
__device__ __align__(256) __nv_bfloat16 g_Klo[(size_t)BB * HH * LL * HD];
__device__ __align__(256) __nv_bfloat16 g_Qhi[(size_t)BB * HH * LL * HD];
__device__ __align__(256) __nv_bfloat16 g_Qlo[(size_t)BB * HH * LL * HD];
__device__ __align__(256) __nv_bfloat16 g_Vthi[(size_t)BB * HH * HD * LL]; // [bh][d][m]
__device__ __align__(256) __nv_bfloat16 g_Vtlo[(size_t)BB * HH * HD * LL];
__device__ float g_wacc[BB * LL];

// ---------------------------------------------------------------------------
__device__ __forceinline__ uint32_t smem_u32(const void* p) {
    uint32_t a;
    asm("{ .reg .u64 t; cvta.to.shared.u64 t, %1; cvt.u32.u64 %0, t; }" : "=r"(a) : "l"(p));
    return a;
}
__device__ __forceinline__ void ldm_x4(uint32_t& r0, uint32_t& r1, uint32_t& r2,
                                       uint32_t& r3, uint32_t addr) {
    asm volatile("ldmatrix.sync.aligned.m8n8.x4.shared.b16 {%0,%1,%2,%3}, [%4];"
                 : "=r"(r0), "=r"(r1), "=r"(r2), "=r"(r3) : "r"(addr));
}
__device__ __forceinline__ void mma_bf16(float& c0, float& c1, float& c2, float& c3,
                                         uint32_t a0, uint32_t a1, uint32_t a2, uint32_t a3,
                                         uint32_t b0, uint32_t b1) {
    asm volatile("mma.sync.aligned.m16n8k16.row.col.f32.bf16.bf16.f32 "
                 "{%0,%1,%2,%3}, {%4,%5,%6,%7}, {%8,%9}, {%0,%1,%2,%3};"
                 : "+f"(c0), "+f"(c1), "+f"(c2), "+f"(c3)
                 : "r"(a0), "r"(a1), "r"(a2), "r"(a3), "r"(b0), "r"(b1));
}

// smem row stride for MMA tiles: 40 bf16 = 80 B; conflict-free ldmatrix.
#define SSTR 40

__device__ __forceinline__ uint16_t bf16_bits(float f) {
    return __bfloat16_as_ushort(__float2bfloat16(f));
}

// ---------------------------------------------------------------------------
// Prep 1: split K,Q fp32 -> bf16 hi/lo in [bh][l][64] layout; zero wacc.
__global__ __launch_bounds__(256) void prep_kq_kernel(
    const float* __restrict__ Kp, const float* __restrict__ Qp)
{
    int idx = blockIdx.x * 256 + threadIdx.x;
    int k = idx & 63, h = (idx >> 6) & 7, l = (idx >> 9) & 1023, b = idx >> 19;
    size_t o = (((size_t)(b * 8 + h) * 1024 + l) << 6) | (unsigned)k;
    float kv = Kp[idx];
    __nv_bfloat16 khi = __float2bfloat16(kv);
    g_Khi[o] = khi;
    g_Klo[o] = __float2bfloat16(kv - __bfloat162float(khi));
    float qv = Qp[idx];
    __nv_bfloat16 qhi = __float2bfloat16(qv);
    g_Qhi[o] = qhi;
    g_Qlo[o] = __float2bfloat16(qv - __bfloat162float(qhi));
    if (idx < BB * LL) g_wacc[idx] = 0.f;
}

// Prep 2: transpose-split V [b][m][h*64+d] -> Vt hi/lo [bh][d][m]
__global__ __launch_bounds__(256) void prep_v_kernel(const float* __restrict__ Vp)
{
    __shared__ float t[32][33];
    int b = blockIdx.z;
    int m0 = blockIdx.x * 32, hd0 = blockIdx.y * 32;
    int tx = threadIdx.x, ty = threadIdx.y;   // (32, 8)
#pragma unroll
    for (int i = 0; i < 4; i++)
        t[ty + 8 * i][tx] = Vp[((size_t)b * 1024 + m0 + ty + 8 * i) * 512 + hd0 + tx];
    __syncthreads();
#pragma unroll
    for (int i = 0; i < 4; i++) {
        int hd = hd0 + ty + 8 * i;
        int h = hd >> 6, d = hd & 63;
        float x = t[tx][ty + 8 * i];
        __nv_bfloat16 hi = __float2bfloat16(x);
        size_t o = ((size_t)(b * 8 + h) * 64 + d) * 1024 + m0 + tx;
        g_Vthi[o] = hi;
        g_Vtlo[o] = __float2bfloat16(x - __bfloat162float(hi));
    }
}

// ---------------------------------------------------------------------------
// GEMM1 (mma.sync bf16): S[bh][l][m] = K[l,:]·Q[m,:], tile 128x128, K=64.
__global__ __launch_bounds__(256) void gemm1_kernel(const float* __restrict__ doc)
{
    __shared__ __nv_bfloat16 sA[2][128 * SSTR];
    __shared__ __nv_bfloat16 sB[2][128 * SSTR];

    int bh = blockIdx.z;
    int b = bh >> 3;
    int len = (int)doc[b];
    int l0 = blockIdx.y * 128, m0 = blockIdx.x * 128;
    if (l0 >= len || m0 >= len) return;

    int tid = threadIdx.x, wid = tid >> 5, lane = tid & 31;
    int wm = (wid >> 2) * 64, wn = (wid & 3) * 32;

    const uint4* srcA[2] = { (const uint4*)(g_Khi + ((size_t)bh * 1024 + l0) * 64),
                             (const uint4*)(g_Klo + ((size_t)bh * 1024 + l0) * 64) };
    const uint4* srcB[2] = { (const uint4*)(g_Qhi + ((size_t)bh * 1024 + m0) * 64),
                             (const uint4*)(g_Qlo + ((size_t)bh * 1024 + m0) * 64) };

    float c[4][4][4];
#pragma unroll
    for (int i = 0; i < 4; i++)
#pragma unroll
        for (int j = 0; j < 4; j++)
#pragma unroll
            for (int q = 0; q < 4; q++) c[i][j][q] = 0.f;

    uint32_t aoff = (uint32_t)(wm + (lane & 15)) * (SSTR * 2) + (((uint32_t)lane >> 4) << 4);
    uint32_t boff = (uint32_t)(wn + (lane & 7) + (((uint32_t)lane >> 4) << 3)) * (SSTR * 2)
                  + ((((uint32_t)lane >> 3) & 1) << 4);
    uint32_t sAh = smem_u32(&sA[0][0]), sAl = smem_u32(&sA[1][0]);
    uint32_t sBh = smem_u32(&sB[0][0]), sBl = smem_u32(&sB[1][0]);

    for (int kc = 0; kc < 64; kc += 32) {
        if (kc) __syncthreads();
#pragma unroll
        for (int e = 0; e < 2; e++) {
#pragma unroll
            for (int i = 0; i < 2; i++) {
                int idx = tid + i * 256;
                int row = idx >> 2, c4 = idx & 3;
                *(uint4*)((char*)&sA[e][0] + row * (SSTR * 2) + c4 * 16) =
                    srcA[e][(size_t)row * 8 + (kc >> 3) + c4];
                *(uint4*)((char*)&sB[e][0] + row * (SSTR * 2) + c4 * 16) =
                    srcB[e][(size_t)row * 8 + (kc >> 3) + c4];
            }
        }
        __syncthreads();

#pragma unroll
        for (int ks = 0; ks < 2; ks++) {
            uint32_t k0b = ks * 32;
            uint32_t Ah[4][4], Al[4][4], Bh[2][4], Bl[2][4];
#pragma unroll
            for (int mt = 0; mt < 4; mt++) {
                ldm_x4(Ah[mt][0], Ah[mt][1], Ah[mt][2], Ah[mt][3],
                       sAh + aoff + mt * 16 * (SSTR * 2) + k0b);
                ldm_x4(Al[mt][0], Al[mt][1], Al[mt][2], Al[mt][3],
                       sAl + aoff + mt * 16 * (SSTR * 2) + k0b);
            }
#pragma unroll
            for (int nt = 0; nt < 2; nt++) {
                ldm_x4(Bh[nt][0], Bh[nt][1], Bh[nt][2], Bh[nt][3],
                       sBh + boff + nt * 16 * (SSTR * 2) + k0b);
                ldm_x4(Bl[nt][0], Bl[nt][1], Bl[nt][2], Bl[nt][3],
                       sBl + boff + nt * 16 * (SSTR * 2) + k0b);
            }
#pragma unroll
            for (int mt = 0; mt < 4; mt++)
#pragma unroll
                for (int ns = 0; ns < 4; ns++) {
                    float* cc = c[mt][ns];
                    uint32_t* bh_ = &Bh[ns >> 1][(ns & 1) * 2];
                    uint32_t* bl_ = &Bl[ns >> 1][(ns & 1) * 2];
                    mma_bf16(cc[0], cc[1], cc[2], cc[3],
                             Ah[mt][0], Ah[mt][1], Ah[mt][2], Ah[mt][3], bh_[0], bh_[1]);
                    mma_bf16(cc[0], cc[1], cc[2], cc[3],
                             Ah[mt][0], Ah[mt][1], Ah[mt][2], Ah[mt][3], bl_[0], bl_[1]);
                    mma_bf16(cc[0], cc[1], cc[2], cc[3],
                             Al[mt][0], Al[mt][1], Al[mt][2], Al[mt][3], bh_[0], bh_[1]);
                }
        }
    }

    float* Sp = g_S + ((size_t)bh * 1024 + l0) * 1024 + m0;
#pragma unroll
    for (int mt = 0; mt < 4; mt++) {
        int r0 = wm + mt * 16 + (lane >> 2);
#pragma unroll
        for (int ns = 0; ns < 4; ns++) {
            int n = wn + ns * 8 + (lane & 3) * 2;
            *(float2*)&Sp[(size_t)r0 * 1024 + n] = make_float2(c[mt][ns][0], c[mt][ns][1]);
            *(float2*)&Sp[(size_t)(r0 + 8) * 1024 + n] = make_float2(c[mt][ns][2], c[mt][ns][3]);
        }
    }
}

// ---------------------------------------------------------------------------
// lnsm v4: max-free softmax. LN output over H=8 heads is bounded (|z| <= 2.47),
// so exp() cannot overflow and softmax's max-subtraction is skipped entirely
// (shift-invariance => numerically exact in fp32 here).
// Pass A (fused): load 8 heads -> LN -> exp -> STS + per-head sum accumulation.
// Tiny block reduction of sums, then Pass B: scale + bf16 hi/lo emit + col sums.
// __launch_bounds__(256, 6) pins occupancy at 6 CTAs/SM (regs capped at 42).
__global__ void __launch_bounds__(256, 6) lnsm_kernel(
    const float* __restrict__ doc, const float* __restrict__ gamma,
    const float* __restrict__ beta)
{
    __shared__ float s[HH][LL];       // 32 KB
    __shared__ float sred[HH][8];
    __shared__ float bout[HH];

    int b = blockIdx.y, l = blockIdx.x;
    int len = (int)doc[b];
    int kend  = (len + 63) & ~63;
    int lceil = (len + 127) & ~127;
    int tid = threadIdx.x;
    int wid = tid >> 5, lane = tid & 31;

    if (l >= len) {                    // zero rows needed by GEMM2
        if (l >= lceil) return;
        int m0 = tid * 4;
        if (m0 < kend) {
            uint2 z = make_uint2(0u, 0u);
#pragma unroll
            for (int h = 0; h < HH; ++h) {
                size_t o = ((size_t)(b * 8 + h) * 1024 + l) * 1024 + m0;
                *(uint2*)(g_Phi + o) = z;
                *(uint2*)(g_Plo + o) = z;
            }
        }
        return;
    }

    const float* Sb = g_S + ((size_t)(b * 8) * 1024 + l) * 1024;
    float ga[HH], be[HH];
#pragma unroll
    for (int h = 0; h < HH; h++) { ga[h] = gamma[h]; be[h] = beta[h]; }

    // ---- pass A: LN + exp + sum, all fused; zeros in [len, kend) ----
    float sm[HH];
#pragma unroll
    for (int h = 0; h < HH; h++) sm[h] = 0.f;

    for (int m = tid; m < LL; m += 256) {
        if (m < len) {
            float x[HH];
#pragma unroll
            for (int h = 0; h < HH; h++) x[h] = Sb[((size_t)h << 20) + m];
            float mu = 0.f;
#pragma unroll
            for (int h = 0; h < HH; h++) mu += x[h];
            mu *= (1.f / HH);
            float var = 0.f;
#pragma unroll
            for (int h = 0; h < HH; h++) { float d0 = x[h] - mu; var += d0 * d0; }
            var *= (1.f / HH);
            float rstd = rsqrtf(var + 1e-5f);
#pragma unroll
            for (int h = 0; h < HH; h++) {
                float e = __expf((x[h] - mu) * rstd * ga[h] + be[h]);  // bounded
                s[h][m] = e;
                sm[h] += e;
            }
        } else if (m < kend) {
#pragma unroll
            for (int h = 0; h < HH; h++) s[h][m] = 0.f;   // prob 0 in pad
        }
    }

    // block-reduce sums per head (8 heads x 8 warps)
#pragma unroll
    for (int h = 0; h < HH; h++) {
#pragma unroll
        for (int o = 16; o; o >>= 1)
            sm[h] += __shfl_xor_sync(0xffffffffu, sm[h], o);
    }
    if (lane == 0) {
#pragma unroll
        for (int h = 0; h < HH; h++) sred[h][wid] = sm[h];
    }
    __syncthreads();                   // also publishes s[][] block-wide
    if (tid < 64) {
        int head = tid >> 3, slot = tid & 7;
        float v = sred[head][slot];
        v += __shfl_xor_sync(0xffffffffu, v, 4);
        v += __shfl_xor_sync(0xffffffffu, v, 2);
        v += __shfl_xor_sync(0xffffffffu, v, 1);
        if (slot == 0) bout[head] = v;
    }
    __syncthreads();

    // ---- pass B: scale + bf16 hi/lo emit + column sums ----
    int m0 = tid * 4;
    if (m0 < kend) {
        float csum[4] = {0.f, 0.f, 0.f, 0.f};
#pragma unroll
        for (int h = 0; h < HH; ++h) {
            float inv = 1.f / bout[h];
            float4 v = *(float4*)&s[h][m0];
            float p0 = v.x * inv, p1 = v.y * inv;
            float p2 = v.z * inv, p3 = v.w * inv;
            csum[0] += p0; csum[1] += p1; csum[2] += p2; csum[3] += p3;
            uint16_t h0 = bf16_bits(p0), h1 = bf16_bits(p1);
            uint16_t h2 = bf16_bits(p2), h3 = bf16_bits(p3);
            uint16_t l0b = bf16_bits(p0 - __bfloat162float(__ushort_as_bfloat16(h0)));
            uint16_t l1b = bf16_bits(p1 - __bfloat162float(__ushort_as_bfloat16(h1)));
            uint16_t l2b = bf16_bits(p2 - __bfloat162float(__ushort_as_bfloat16(h2)));
            uint16_t l3b = bf16_bits(p3 - __bfloat162float(__ushort_as_bfloat16(h3)));
            size_t o = ((size_t)(b * 8 + h) * 1024 + l) * 1024 + m0;
            *(uint2*)(g_Phi + o) = make_uint2((uint32_t)h0 | ((uint32_t)h1 << 16),
                                              (uint32_t)h2 | ((uint32_t)h3 << 16));
            *(uint2*)(g_Plo + o) = make_uint2((uint32_t)l0b | ((uint32_t)l1b << 16),
                                              (uint32_t)l2b | ((uint32_t)l3b << 16));
        }
#pragma unroll
        for (int mi = 0; mi < 4; mi++)
            if (m0 + mi < len) atomicAdd(&g_wacc[b * 1024 + m0 + mi], csum[mi]);
    }
}

// ---------------------------------------------------------------------------
// Finalize w: one 1024-thread block per batch, single pass.
__global__ __launch_bounds__(1024) void wfin_kernel(
    const float* __restrict__ doc, float* __restrict__ wout)
{
    __shared__ float red[32];
    __shared__ float s_bmax, s_inv;
    int b = blockIdx.x;
    int len = (int)doc[b];
    int tid = threadIdx.x, w = tid >> 5, lane = tid & 31;
    float scale = 1.f / (8.f * (float)len);

    float v = (tid < len) ? g_wacc[b * LL + tid] * scale : -1e30f;
    float mx = v;
#pragma unroll
    for (int o = 16; o; o >>= 1) mx = fmaxf(mx, __shfl_xor_sync(0xffffffffu, mx, o));
    if (lane == 0) red[w] = mx;
    __syncthreads();
    if (w == 0) {
        float t = red[lane];
#pragma unroll
        for (int o = 16; o; o >>= 1) t = fmaxf(t, __shfl_xor_sync(0xffffffffu, t, o));
        if (lane == 0) s_bmax = t;
    }
    __syncthreads();
    float e = (tid < len) ? __expf(v - s_bmax) : 0.f;
    float sum = e;
#pragma unroll
    for (int o = 16; o; o >>= 1) sum += __shfl_xor_sync(0xffffffffu, sum, o);
    if (lane == 0) red[w] = sum;
    __syncthreads();
    if (w == 0) {
        float t = red[lane];
#pragma unroll
        for (int o = 16; o; o >>= 1) t += __shfl_xor_sync(0xffffffffu, t, o);
        if (lane == 0) s_inv = 1.f / t;
    }
    __syncthreads();
    wout[b * LL + tid] = e * s_inv;
}

// ---------------------------------------------------------------------------
// GEMM2 (mma.sync bf16): out[l,d] = sum_m P[l,m]·Vt[d,m]; tile 128(l) x 64(d).
// Register-prefetch pipeline over K chunks of 32 (next chunk's LDGs overlap MMA).
__global__ __launch_bounds__(256) void gemm2_kernel(
    const float* __restrict__ doc, float* __restrict__ outp)
{
    __shared__ __nv_bfloat16 sP[2][128 * SSTR];
    __shared__ __nv_bfloat16 sV[2][64 * SSTR];

    int b = blockIdx.z, h = blockIdx.y;
    int bh = b * 8 + h;
    int len = (int)doc[b];
    int l0 = blockIdx.x * 128;
    int tid = threadIdx.x, wid = tid >> 5, lane = tid & 31;

    if (l0 >= len) {
        float* dst = outp + ((size_t)b * 1024 + l0 + (tid >> 1)) * 512 + h * 64;
        float4 z = make_float4(0, 0, 0, 0);
#pragma unroll
        for (int j = 0; j < 8; j++) ((float4*)dst)[(tid & 1) * 8 + j] = z;
        return;
    }

    int wm = (wid >> 1) * 32, wn = (wid & 1) * 32;

    const uint4* srcP[2] = { (const uint4*)(g_Phi + ((size_t)bh * 1024 + l0) * 1024),
                             (const uint4*)(g_Plo + ((size_t)bh * 1024 + l0) * 1024) };
    const uint4* srcV[2] = { (const uint4*)(g_Vthi + (size_t)bh * 64 * 1024),
                             (const uint4*)(g_Vtlo + (size_t)bh * 64 * 1024) };

    float c[2][4][4];
#pragma unroll
    for (int i = 0; i < 2; i++)
#pragma unroll
        for (int j = 0; j < 4; j++)
#pragma unroll
            for (int q = 0; q < 4; q++) c[i][j][q] = 0.f;

    uint32_t aoff = (uint32_t)(wm + (lane & 15)) * (SSTR * 2) + (((uint32_t)lane >> 4) << 4);
    uint32_t boff = (uint32_t)(wn + (lane & 7) + (((uint32_t)lane >> 4) << 3)) * (SSTR * 2)
                  + ((((uint32_t)lane >> 3) & 1) << 4);
    uint32_t sPh = smem_u32(&sP[0][0]), sPl = smem_u32(&sP[1][0]);
    uint32_t sVh = smem_u32(&sV[0][0]), sVl = smem_u32(&sV[1][0]);

    int prow = tid >> 2, pc4 = tid & 3;
    int vrow = tid >> 2, vc4 = tid & 3;
    char* stP[2][2];
    char* stV[2];
#pragma unroll
    for (int e = 0; e < 2; e++) {
        stP[e][0] = (char*)&sP[e][0] + prow * (SSTR * 2) + pc4 * 16;
        stP[e][1] = (char*)&sP[e][0] + (prow + 64) * (SSTR * 2) + pc4 * 16;
        stV[e]    = (char*)&sV[e][0] + vrow * (SSTR * 2) + vc4 * 16;
    }

    int kend = (len + 31) & ~31;
    int nch = kend >> 5;

    uint4 rp[2][2], rv[2];
#pragma unroll
    for (int e = 0; e < 2; e++) {
        rp[e][0] = srcP[e][(size_t)prow * 128 + pc4];
        rp[e][1] = srcP[e][(size_t)(prow + 64) * 128 + pc4];
        rv[e]    = srcV[e][(size_t)vrow * 128 + vc4];
    }

    for (int ch = 0; ch < nch; ++ch) {
#pragma unroll
        for (int e = 0; e < 2; e++) {
            *(uint4*)stP[e][0] = rp[e][0];
            *(uint4*)stP[e][1] = rp[e][1];
            *(uint4*)stV[e]    = rv[e];
        }
        __syncthreads();

        if (ch + 1 < nch) {
            int mq = (ch + 1) * 4;
#pragma unroll
            for (int e = 0; e < 2; e++) {
                rp[e][0] = srcP[e][(size_t)prow * 128 + mq + pc4];
                rp[e][1] = srcP[e][(size_t)(prow + 64) * 128 + mq + pc4];
                rv[e]    = srcV[e][(size_t)vrow * 128 + mq + vc4];
            }
        }

#pragma unroll
        for (int ks = 0; ks < 2; ks++) {
            uint32_t k0b = ks * 32;
            uint32_t Ah[2][4], Al[2][4], Bh[2][4], Bl[2][4];
#pragma unroll
            for (int mt = 0; mt < 2; mt++) {
                ldm_x4(Ah[mt][0], Ah[mt][1], Ah[mt][2], Ah[mt][3],
                       sPh + aoff + mt * 16 * (SSTR * 2) + k0b);
                ldm_x4(Al[mt][0], Al[mt][1], Al[mt][2], Al[mt][3],
                       sPl + aoff + mt * 16 * (SSTR * 2) + k0b);
            }
#pragma unroll
            for (int nt = 0; nt < 2; nt++) {
                ldm_x4(Bh[nt][0], Bh[nt][1], Bh[nt][2], Bh[nt][3],
                       sVh + boff + nt * 16 * (SSTR * 2) + k0b);
                ldm_x4(Bl[nt][0], Bl[nt][1], Bl[nt][2], Bl[nt][3],
                       sVl + boff + nt * 16 * (SSTR * 2) + k0b);
            }
#pragma unroll
            for (int mt = 0; mt < 2; mt++)
#pragma unroll
                for (int ns = 0; ns < 4; ns++) {
                    float* cc = c[mt][ns];
                    uint32_t* bh_ = &Bh[ns >> 1][(ns & 1) * 2];
                    uint32_t* bl_ = &Bl[ns >> 1][(ns & 1) * 2];
                    mma_bf16(cc[0], cc[1], cc[2], cc[3],
                             Ah[mt][0], Ah[mt][1], Ah[mt][2], Ah[mt][3], bh_[0], bh_[1]);
                    mma_bf16(cc[0], cc[1], cc[2], cc[3],
                             Ah[mt][0], Ah[mt][1], Ah[mt][2], Ah[mt][3], bl_[0], bl_[1]);
                    mma_bf16(cc[0], cc[1], cc[2], cc[3],
                             Al[mt][0], Al[mt][1], Al[mt][2], Al[mt][3], bh_[0], bh_[1]);
                }
        }
        __syncthreads();
    }

    float* dstb = outp + ((size_t)b * 1024 + l0) * 512 + h * 64;
#pragma unroll
    for (int mt = 0; mt < 2; mt++) {
        int r0 = wm + mt * 16 + (lane >> 2);
#pragma unroll
        for (int ns = 0; ns < 4; ns++) {
            int n = wn + ns * 8 + (lane & 3) * 2;
            *(float2*)&dstb[(size_t)r0 * 512 + n] = make_float2(c[mt][ns][0], c[mt][ns][1]);
            *(float2*)&dstb[(size_t)(r0 + 8) * 512 + n] = make_float2(c[mt][ns][2], c[mt][ns][3]);
        }
    }
}

// ---------------------------------------------------------------------------
extern "C" void kernel_launch(void* const* d_in, const int* in_sizes, int n_in,
                              void* d_out, int out_size) {
    const float* K     = (const float*)d_in[0];
    const float* Q     = (const float*)d_in[1];
    const float* V     = (const float*)d_in[2];
    const float* doc   = (const float*)d_in[3];
    const float* gamma = (const float*)d_in[4];
    const float* beta  = (const float*)d_in[5];
    // pad_mask / bx_packed derivable from doc_sizes; unused.

    float* outp = (float*)d_out;

    prep_kq_kernel<<<(BB * LL * DD) / 256, 256>>>(K, Q);
    prep_v_kernel<<<dim3(LL / 32, DD / 32, BB), dim3(32, 8)>>>(V);

    dim3 g1(LL / 128, LL / 128, BB * HH);      // (8, 8, 32)
    gemm1_kernel<<<g1, 256>>>(doc);

    dim3 g2(LL, BB);
    lnsm_kernel<<<g2, 256>>>(doc, gamma, beta);

    if (out_size >= BB * LL * DD + BB * LL) {
        float* wout = outp + (size_t)BB * LL * DD;
        wfin_kernel<<<BB, 1024>>>(doc, wout);
    }

    dim3 g3(LL / 128, HH, BB);                 // (8, 8, 4)
    gemm2_kernel<<<g3, 256>>>(doc, outp);
}